// round 8
// baseline (speedup 1.0000x reference)
#include <cuda_runtime.h>
#include <cuda_bf16.h>

#define BATCH 32
#define KVH 8
#define G 4
#define HD 128
#define PS 16
#define L0P 256
#define L1P 64
#define L2P 32
#define ATT_SCALE 0.08838834764831845f

// Part A (level 0, shared prefix): 4 batch-groups x 8 kvh x 16 chunks (16 pages = 256 tok)
#define A_BG 4
#define A_BPG 8
#define A_CHP 16
#define A_NCH 16
#define A_BLOCKS (A_BG * KVH * A_NCH)          // 512
// Part B (levels 1+2, per-seq): 32 b x 8 kvh x 3 chunks (32 pages = 512 tok)
#define B_CHP 32
#define B_NCH 3
#define B_BLOCKS (BATCH * KVH * B_NCH)         // 768
#define NCH_TOT (A_NCH + B_NCH)                // 19 partials per (b,kvh)

// unnormalized partial sums (fixed m=0 softmax; merge = plain add)
__device__ float g_po[(size_t)BATCH * KVH * NCH_TOT * G * HD];   // ~10 MB
__device__ float g_pl[(size_t)BATCH * KVH * NCH_TOT * G];

union F2u { float2 f2; unsigned long long u; };
__device__ __forceinline__ float2 ffma2(float2 a, float2 b, float2 c) {
    F2u A, B, C, R; A.f2 = a; B.f2 = b; C.f2 = c;
    asm("fma.rn.f32x2 %0, %1, %2, %3;" : "=l"(R.u) : "l"(A.u), "l"(B.u), "l"(C.u));
    return R.f2;
}
__device__ __forceinline__ float2 fmul2(float2 a, float2 b) {
    F2u A, B, R; A.f2 = a; B.f2 = b;
    asm("mul.rn.f32x2 %0, %1, %2;" : "=l"(R.u) : "l"(A.u), "l"(B.u));
    return R.f2;
}

// reduce s[0..3] over the 16-lane half; ONE exp per lane (lane owns g=lane&3).
// lanes {x,x+4,x+8,x+12} hold IDENTICAL lpart copies -> final cross-half
// combine must be ONLY shfl_xor 16.
__device__ __forceinline__ void half_softmax(float s[4], int lane, float& lpart,
                                             float& e0, float& e1, float& e2, float& e3)
{
    #pragma unroll
    for (int off = 1; off <= 2; off <<= 1) {
        #pragma unroll
        for (int g = 0; g < 4; g++) s[g] += __shfl_xor_sync(0xffffffffu, s[g], off);
    }
    const int mg = lane & 3;
    float r = (mg == 0) ? s[0] : (mg == 1) ? s[1] : (mg == 2) ? s[2] : s[3];
    r += __shfl_xor_sync(0xffffffffu, r, 4);
    r += __shfl_xor_sync(0xffffffffu, r, 8);
    float e = __expf(r);
    lpart += e;
    const int base = lane & 16;
    e0 = __shfl_sync(0xffffffffu, e, base | 0);
    e1 = __shfl_sync(0xffffffffu, e, base | 1);
    e2 = __shfl_sync(0xffffffffu, e, base | 2);
    e3 = __shfl_sync(0xffffffffu, e, base | 3);
}

__global__ __launch_bounds__(256, 2)
void cascade_phase1(const float* __restrict__ q,
                    const float* __restrict__ kv,
                    const int* __restrict__ sp,
                    const int* __restrict__ p1,
                    const int* __restrict__ p2)
{
    __shared__ float sbuf[8192];
    __shared__ float s_l[8 * G];
    __shared__ int   pages_s[32];

    const int tid  = threadIdx.x;
    const int warp = tid >> 5;
    const int lane = tid & 31;
    const int half = lane >> 4;
    const int lr   = lane & 15;

    // interleave A:B = 2:3 (512 A, 768 B) so compute-bound A and DRAM-bound B co-execute
    const int bx   = blockIdx.x;
    const int grp  = bx / 5;
    const int rem  = bx - grp * 5;
    const bool isA = (rem < 2);

    const size_t KVROW = (size_t)KVH * HD;
    const size_t VOFF  = (size_t)PS * KVH * HD;
    const size_t PGSTR = 2 * VOFF;

    if (isA) {
        // ============ Part A: shared prefix, 8 batches per block, 256 tok ============
        const int a   = grp * 2 + rem;            // 0..511
        const int bg  = a & (A_BG - 1);
        const int kvh = (a >> 2) & (KVH - 1);
        const int ch  = a >> 5;                   // 0..15
        const int b   = bg * A_BPG + warp;

        if (tid < A_CHP) pages_s[tid] = sp[ch * A_CHP + tid];

        float2 qr[G][4];
        {
            const float* qb = q + ((size_t)b * KVH + kvh) * G * HD;
            #pragma unroll
            for (int g = 0; g < G; g++) {
                float4 x = *(const float4*)(qb + g * HD + lr * 4);
                float4 y = *(const float4*)(qb + g * HD + 64 + lr * 4);
                qr[g][0] = make_float2(x.x * ATT_SCALE, x.y * ATT_SCALE);
                qr[g][1] = make_float2(x.z * ATT_SCALE, x.w * ATT_SCALE);
                qr[g][2] = make_float2(y.x * ATT_SCALE, y.y * ATT_SCALE);
                qr[g][3] = make_float2(y.z * ATT_SCALE, y.w * ATT_SCALE);
            }
        }
        __syncthreads();

        float lpart = 0.f;
        float2 acc[G][4];
        #pragma unroll
        for (int g = 0; g < G; g++)
            #pragma unroll
            for (int j = 0; j < 4; j++) acc[g][j] = make_float2(0.f, 0.f);

        float* sK = sbuf;
        float* sV = sbuf + 4096;

        auto load_tile = [&](int tt, int buf) {
            const int pg = pages_s[tt];
            const float* base = kv + (size_t)pg * PGSTR + (size_t)kvh * HD;
            #pragma unroll
            for (int j = 0; j < 2; j++) {
                int idx = tid + j * 256;
                int tp  = idx >> 5, seg = idx & 31;
                float4 kk = *(const float4*)(base + (size_t)tp * KVROW + seg * 4);
                float4 vv = *(const float4*)(base + VOFF + (size_t)tp * KVROW + seg * 4);
                *(float4*)(sK + buf * 2048 + tp * 128 + seg * 4) = kk;
                *(float4*)(sV + buf * 2048 + tp * 128 + seg * 4) = vv;
            }
        };

        load_tile(0, 0);
        __syncthreads();

        for (int tt = 0; tt < A_CHP; tt++) {
            if (tt + 1 < A_CHP) load_tile(tt + 1, (tt + 1) & 1);
            const int buf = tt & 1;
            #pragma unroll
            for (int it = 0; it < 16; it += 2) {
                const int tok = it + half;
                const float* kr = sK + buf * 2048 + tok * 128;
                const float* vr = sV + buf * 2048 + tok * 128;
                float4 k0 = *(const float4*)(kr + lr * 4);
                float4 k1 = *(const float4*)(kr + 64 + lr * 4);
                float4 v0 = *(const float4*)(vr + lr * 4);
                float4 v1 = *(const float4*)(vr + 64 + lr * 4);

                float2 kp[4] = { make_float2(k0.x,k0.y), make_float2(k0.z,k0.w),
                                 make_float2(k1.x,k1.y), make_float2(k1.z,k1.w) };
                float2 vp[4] = { make_float2(v0.x,v0.y), make_float2(v0.z,v0.w),
                                 make_float2(v1.x,v1.y), make_float2(v1.z,v1.w) };

                float s[G];
                #pragma unroll
                for (int g = 0; g < G; g++) {
                    float2 t = fmul2(qr[g][0], kp[0]);
                    t = ffma2(qr[g][1], kp[1], t);
                    t = ffma2(qr[g][2], kp[2], t);
                    t = ffma2(qr[g][3], kp[3], t);
                    s[g] = t.x + t.y;
                }
                float e0, e1, e2, e3;
                half_softmax(s, lane, lpart, e0, e1, e2, e3);
                #pragma unroll
                for (int j = 0; j < 4; j++) {
                    acc[0][j] = ffma2(make_float2(e0, e0), vp[j], acc[0][j]);
                    acc[1][j] = ffma2(make_float2(e1, e1), vp[j], acc[1][j]);
                    acc[2][j] = ffma2(make_float2(e2, e2), vp[j], acc[2][j]);
                    acc[3][j] = ffma2(make_float2(e3, e3), vp[j], acc[3][j]);
                }
            }
            __syncthreads();
        }

        // merge the two half-warp token-splits (lpart: ONLY shfl 16)
        #pragma unroll
        for (int g = 0; g < G; g++)
            #pragma unroll
            for (int j = 0; j < 4; j++) {
                acc[g][j].x += __shfl_xor_sync(0xffffffffu, acc[g][j].x, 16);
                acc[g][j].y += __shfl_xor_sync(0xffffffffu, acc[g][j].y, 16);
            }
        lpart += __shfl_xor_sync(0xffffffffu, lpart, 16);
        // lanes 0..3 now hold l[g = lane]

        const size_t obase = (((size_t)b * KVH + kvh) * NCH_TOT + ch) * (size_t)(G * HD);
        const size_t lbase = (((size_t)b * KVH + kvh) * NCH_TOT + ch) * (size_t)G;
        if (half == 0) {
            #pragma unroll
            for (int g = 0; g < G; g++)
                #pragma unroll
                for (int j = 0; j < 4; j++) {
                    int d = (j < 2 ? 0 : 64) + lr * 4 + (j & 1) * 2;
                    *(float2*)(g_po + obase + g * HD + d) = acc[g][j];
                }
            if (lr < 4) g_pl[lbase + lr] = lpart;
        }
    } else {
        // ============ Part B: levels 1+2, per-sequence, 512 tok ============
        const int bidx = grp * 3 + (rem - 2);     // 0..767
        const int b    = bidx & (BATCH - 1);
        const int kvh  = (bidx >> 5) & (KVH - 1);
        const int ch   = bidx >> 8;               // 0..2

        if (tid < B_CHP) {
            int vp = ch * B_CHP + tid;
            pages_s[tid] = (vp < L1P) ? p1[b * L1P + vp] : p2[b * L2P + (vp - L1P)];
        }

        float2 qr[G][4];
        {
            const float* qb = q + ((size_t)b * KVH + kvh) * G * HD;
            #pragma unroll
            for (int g = 0; g < G; g++) {
                float4 x = *(const float4*)(qb + g * HD + lr * 4);
                float4 y = *(const float4*)(qb + g * HD + 64 + lr * 4);
                qr[g][0] = make_float2(x.x * ATT_SCALE, x.y * ATT_SCALE);
                qr[g][1] = make_float2(x.z * ATT_SCALE, x.w * ATT_SCALE);
                qr[g][2] = make_float2(y.x * ATT_SCALE, y.y * ATT_SCALE);
                qr[g][3] = make_float2(y.z * ATT_SCALE, y.w * ATT_SCALE);
            }
        }
        __syncthreads();

        float lpart = 0.f;
        float2 acc[G][4];
        #pragma unroll
        for (int g = 0; g < G; g++)
            #pragma unroll
            for (int j = 0; j < 4; j++) acc[g][j] = make_float2(0.f, 0.f);

        auto rowptr = [&](int tok) -> const float* {
            int pg = pages_s[tok >> 4];
            int tp = tok & 15;
            return kv + (size_t)pg * PGSTR + (size_t)tp * KVROW + (size_t)kvh * HD;
        };

        const int mytok = warp * 2 + half;
        const float* p = rowptr(mytok);
        float4 k0 = *(const float4*)(p + lr * 4);
        float4 k1 = *(const float4*)(p + 64 + lr * 4);
        float4 v0 = *(const float4*)(p + VOFF + lr * 4);
        float4 v1 = *(const float4*)(p + VOFF + 64 + lr * 4);

        for (int it = 16; it <= 512; it += 16) {
            float4 nk0, nk1, nv0, nv1;
            if (it < 512) {
                const float* np = rowptr(it + mytok);
                nk0 = *(const float4*)(np + lr * 4);
                nk1 = *(const float4*)(np + 64 + lr * 4);
                nv0 = *(const float4*)(np + VOFF + lr * 4);
                nv1 = *(const float4*)(np + VOFF + 64 + lr * 4);
            }

            float2 kp[4] = { make_float2(k0.x,k0.y), make_float2(k0.z,k0.w),
                             make_float2(k1.x,k1.y), make_float2(k1.z,k1.w) };
            float2 vp[4] = { make_float2(v0.x,v0.y), make_float2(v0.z,v0.w),
                             make_float2(v1.x,v1.y), make_float2(v1.z,v1.w) };

            float s[G];
            #pragma unroll
            for (int g = 0; g < G; g++) {
                float2 t = fmul2(qr[g][0], kp[0]);
                t = ffma2(qr[g][1], kp[1], t);
                t = ffma2(qr[g][2], kp[2], t);
                t = ffma2(qr[g][3], kp[3], t);
                s[g] = t.x + t.y;
            }
            float e0, e1, e2, e3;
            half_softmax(s, lane, lpart, e0, e1, e2, e3);
            #pragma unroll
            for (int j = 0; j < 4; j++) {
                acc[0][j] = ffma2(make_float2(e0, e0), vp[j], acc[0][j]);
                acc[1][j] = ffma2(make_float2(e1, e1), vp[j], acc[1][j]);
                acc[2][j] = ffma2(make_float2(e2, e2), vp[j], acc[2][j]);
                acc[3][j] = ffma2(make_float2(e3, e3), vp[j], acc[3][j]);
            }

            k0 = nk0; k1 = nk1; v0 = nv0; v1 = nv1;
        }

        // merge halves (lpart: ONLY shfl 16)
        #pragma unroll
        for (int g = 0; g < G; g++)
            #pragma unroll
            for (int j = 0; j < 4; j++) {
                acc[g][j].x += __shfl_xor_sync(0xffffffffu, acc[g][j].x, 16);
                acc[g][j].y += __shfl_xor_sync(0xffffffffu, acc[g][j].y, 16);
            }
        lpart += __shfl_xor_sync(0xffffffffu, lpart, 16);

        if (half == 0) {
            #pragma unroll
            for (int g = 0; g < G; g++)
                #pragma unroll
                for (int j = 0; j < 4; j++) {
                    int d = (j < 2 ? 0 : 64) + lr * 4 + (j & 1) * 2;
                    *(float2*)(sbuf + warp * 512 + g * HD + d) = acc[g][j];
                }
            if (lr < 4) s_l[warp * G + lr] = lpart;
        }
        __syncthreads();

        const size_t obase = (((size_t)b * KVH + kvh) * NCH_TOT + (A_NCH + ch)) * (size_t)(G * HD);
        const size_t lbase = (((size_t)b * KVH + kvh) * NCH_TOT + (A_NCH + ch)) * (size_t)G;
        #pragma unroll
        for (int pidx = 0; pidx < 2; pidx++) {
            int p2i = tid + pidx * 256;
            float O = 0.f;
            #pragma unroll
            for (int w = 0; w < 8; w++) O += sbuf[w * 512 + p2i];
            g_po[obase + p2i] = O;
        }
        if (tid < G) {
            float L = 0.f;
            #pragma unroll
            for (int w = 0; w < 8; w++) L += s_l[w * G + tid];
            g_pl[lbase + tid] = L;
        }
    }
}

__global__ __launch_bounds__(512)
void cascade_phase2(float* __restrict__ out)
{
    const int b   = blockIdx.x;
    const int kvh = blockIdx.y;
    const int t   = threadIdx.x;
    const int sub = t >> 8;               // 0/1 chunk-split
    const int idx = t & 255;              // (g, d2) pair
    const int g   = idx >> 6;             // 0..3
    const int d2  = idx & 63;             // float2 slot 0..63

    __shared__ float spl[NCH_TOT * G];
    __shared__ float2 sred[256];
    if (t < NCH_TOT * G)
        spl[t] = g_pl[((size_t)b * KVH + kvh) * NCH_TOT * G + t];
    __syncthreads();

    float L = 0.f;
    #pragma unroll
    for (int ch = 0; ch < NCH_TOT; ch++) L += spl[ch * G + g];
    const float inv = 1.f / L;

    const float* pb = g_po + ((size_t)b * KVH + kvh) * NCH_TOT * (size_t)(G * HD)
                           + (size_t)g * HD + d2 * 2;
    float2 O = make_float2(0.f, 0.f);
    #pragma unroll
    for (int ch = sub; ch < NCH_TOT; ch += 2) {
        float2 v = *(const float2*)(pb + (size_t)ch * (G * HD));
        O.x += v.x; O.y += v.y;
    }
    if (sub == 1) sred[idx] = O;
    __syncthreads();
    if (sub == 0) {
        O.x = (O.x + sred[idx].x) * inv;
        O.y = (O.y + sred[idx].y) * inv;
        *(float2*)(out + ((size_t)b * KVH + kvh) * G * HD + (size_t)g * HD + d2 * 2) = O;
    }
}

extern "C" void kernel_launch(void* const* d_in, const int* in_sizes, int n_in,
                              void* d_out, int out_size)
{
    const float* q  = (const float*)d_in[0];
    const float* kv = (const float*)d_in[1];
    const int*   sp = (const int*)d_in[2];
    const int*   p1 = (const int*)d_in[3];
    const int*   p2 = (const int*)d_in[4];
    float* out = (float*)d_out;

    cascade_phase1<<<A_BLOCKS + B_BLOCKS, 256>>>(q, kv, sp, p1, p2);
    cascade_phase2<<<dim3(BATCH, KVH), 512>>>(out);
}

// round 10
// speedup vs baseline: 1.5015x; 1.5015x over previous
#include <cuda_runtime.h>
#include <cuda_bf16.h>

#define BATCH 32
#define KVH 8
#define G 4
#define HD 128
#define PS 16
#define L0P 256
#define L1P 64
#define L2P 32
#define ATT_SCALE 0.08838834764831845f

// Part A (level 0, shared prefix): 4 batch-groups x 8 kvh x 64 chunks (4 pages = 64 tok)
#define A_BG 4
#define A_BPG 8
#define A_CHP 4
#define A_NCH 64
#define A_BLOCKS (A_BG * KVH * A_NCH)          // 2048
// Part B (levels 1+2, per-seq): 32 b x 8 kvh x 6 chunks (16 pages = 256 tok)
#define B_CHP 16
#define B_NCH 6
#define B_BLOCKS (BATCH * KVH * B_NCH)         // 1536
#define NCH_TOT (A_NCH + B_NCH)                // 70 partials per (b,kvh)

// unnormalized partial sums (fixed m=0 softmax; merge = plain add)
__device__ float g_po[(size_t)BATCH * KVH * NCH_TOT * G * HD];
__device__ float g_pl[(size_t)BATCH * KVH * NCH_TOT * G];

union F2u { float2 f2; unsigned long long u; };
__device__ __forceinline__ float2 ffma2(float2 a, float2 b, float2 c) {
    F2u A, B, C, R; A.f2 = a; B.f2 = b; C.f2 = c;
    asm("fma.rn.f32x2 %0, %1, %2, %3;" : "=l"(R.u) : "l"(A.u), "l"(B.u), "l"(C.u));
    return R.f2;
}
__device__ __forceinline__ float2 fmul2(float2 a, float2 b) {
    F2u A, B, R; A.f2 = a; B.f2 = b;
    asm("mul.rn.f32x2 %0, %1, %2;" : "=l"(R.u) : "l"(A.u), "l"(B.u));
    return R.f2;
}

// reduce s[0..3] over the 16-lane half; ONE exp per lane (lane owns g=lane&3).
// lanes {x,x+4,x+8,x+12} hold IDENTICAL lpart copies -> final cross-half
// combine must be ONLY shfl_xor 16.
__device__ __forceinline__ void half_softmax(float s[4], int lane, float& lpart,
                                             float& e0, float& e1, float& e2, float& e3)
{
    #pragma unroll
    for (int off = 1; off <= 2; off <<= 1) {
        #pragma unroll
        for (int g = 0; g < 4; g++) s[g] += __shfl_xor_sync(0xffffffffu, s[g], off);
    }
    const int mg = lane & 3;
    float r = (mg == 0) ? s[0] : (mg == 1) ? s[1] : (mg == 2) ? s[2] : s[3];
    r += __shfl_xor_sync(0xffffffffu, r, 4);
    r += __shfl_xor_sync(0xffffffffu, r, 8);
    float e = __expf(r);
    lpart += e;
    const int base = lane & 16;
    e0 = __shfl_sync(0xffffffffu, e, base | 0);
    e1 = __shfl_sync(0xffffffffu, e, base | 1);
    e2 = __shfl_sync(0xffffffffu, e, base | 2);
    e3 = __shfl_sync(0xffffffffu, e, base | 3);
}

__global__ __launch_bounds__(256, 2)
void cascade_phase1(const float* __restrict__ q,
                    const float* __restrict__ kv,
                    const int* __restrict__ sp,
                    const int* __restrict__ p1,
                    const int* __restrict__ p2)
{
    __shared__ float sbuf[8192];
    __shared__ float s_l[8 * G];
    __shared__ int   pages_s[16];

    const int tid  = threadIdx.x;
    const int warp = tid >> 5;
    const int lane = tid & 31;
    const int half = lane >> 4;
    const int lr   = lane & 15;

    // interleave A:B = 4:3 so compute-bound A and DRAM-bound B co-execute
    const int bx   = blockIdx.x;
    const int grp  = bx / 7;
    const int rem  = bx - grp * 7;
    const bool isA = (rem < 4);

    const size_t KVROW = (size_t)KVH * HD;
    const size_t VOFF  = (size_t)PS * KVH * HD;
    const size_t PGSTR = 2 * VOFF;

    if (isA) {
        // ============ Part A: shared prefix, 8 batches per block ============
        const int a   = grp * 4 + rem;
        const int bg  = a & (A_BG - 1);
        const int kvh = (a >> 2) & (KVH - 1);
        const int ch  = a >> 5;
        const int b   = bg * A_BPG + warp;

        if (tid < A_CHP) pages_s[tid] = sp[ch * A_CHP + tid];

        float2 qr[G][4];
        {
            const float* qb = q + ((size_t)b * KVH + kvh) * G * HD;
            #pragma unroll
            for (int g = 0; g < G; g++) {
                float4 x = *(const float4*)(qb + g * HD + lr * 4);
                float4 y = *(const float4*)(qb + g * HD + 64 + lr * 4);
                qr[g][0] = make_float2(x.x * ATT_SCALE, x.y * ATT_SCALE);
                qr[g][1] = make_float2(x.z * ATT_SCALE, x.w * ATT_SCALE);
                qr[g][2] = make_float2(y.x * ATT_SCALE, y.y * ATT_SCALE);
                qr[g][3] = make_float2(y.z * ATT_SCALE, y.w * ATT_SCALE);
            }
        }
        __syncthreads();

        float lpart = 0.f;
        float2 acc[G][4];
        #pragma unroll
        for (int g = 0; g < G; g++)
            #pragma unroll
            for (int j = 0; j < 4; j++) acc[g][j] = make_float2(0.f, 0.f);

        float* sK = sbuf;
        float* sV = sbuf + 4096;

        auto load_tile = [&](int tt, int buf) {
            const int pg = pages_s[tt];
            const float* base = kv + (size_t)pg * PGSTR + (size_t)kvh * HD;
            #pragma unroll
            for (int j = 0; j < 2; j++) {
                int idx = tid + j * 256;
                int tp  = idx >> 5, seg = idx & 31;
                float4 kk = *(const float4*)(base + (size_t)tp * KVROW + seg * 4);
                float4 vv = *(const float4*)(base + VOFF + (size_t)tp * KVROW + seg * 4);
                *(float4*)(sK + buf * 2048 + tp * 128 + seg * 4) = kk;
                *(float4*)(sV + buf * 2048 + tp * 128 + seg * 4) = vv;
            }
        };

        load_tile(0, 0);
        __syncthreads();

        for (int tt = 0; tt < A_CHP; tt++) {
            if (tt + 1 < A_CHP) load_tile(tt + 1, (tt + 1) & 1);
            const int buf = tt & 1;
            #pragma unroll
            for (int it = 0; it < 16; it += 2) {
                const int tok = it + half;
                const float* kr = sK + buf * 2048 + tok * 128;
                const float* vr = sV + buf * 2048 + tok * 128;
                float4 k0 = *(const float4*)(kr + lr * 4);
                float4 k1 = *(const float4*)(kr + 64 + lr * 4);
                float4 v0 = *(const float4*)(vr + lr * 4);
                float4 v1 = *(const float4*)(vr + 64 + lr * 4);

                float2 kp[4] = { make_float2(k0.x,k0.y), make_float2(k0.z,k0.w),
                                 make_float2(k1.x,k1.y), make_float2(k1.z,k1.w) };
                float2 vp[4] = { make_float2(v0.x,v0.y), make_float2(v0.z,v0.w),
                                 make_float2(v1.x,v1.y), make_float2(v1.z,v1.w) };

                float s[G];
                #pragma unroll
                for (int g = 0; g < G; g++) {
                    float2 t = fmul2(qr[g][0], kp[0]);
                    t = ffma2(qr[g][1], kp[1], t);
                    t = ffma2(qr[g][2], kp[2], t);
                    t = ffma2(qr[g][3], kp[3], t);
                    s[g] = t.x + t.y;
                }
                float e0, e1, e2, e3;
                half_softmax(s, lane, lpart, e0, e1, e2, e3);
                #pragma unroll
                for (int j = 0; j < 4; j++) {
                    acc[0][j] = ffma2(make_float2(e0, e0), vp[j], acc[0][j]);
                    acc[1][j] = ffma2(make_float2(e1, e1), vp[j], acc[1][j]);
                    acc[2][j] = ffma2(make_float2(e2, e2), vp[j], acc[2][j]);
                    acc[3][j] = ffma2(make_float2(e3, e3), vp[j], acc[3][j]);
                }
            }
            __syncthreads();
        }

        // merge the two half-warp token-splits (lpart: ONLY shfl 16)
        #pragma unroll
        for (int g = 0; g < G; g++)
            #pragma unroll
            for (int j = 0; j < 4; j++) {
                acc[g][j].x += __shfl_xor_sync(0xffffffffu, acc[g][j].x, 16);
                acc[g][j].y += __shfl_xor_sync(0xffffffffu, acc[g][j].y, 16);
            }
        lpart += __shfl_xor_sync(0xffffffffu, lpart, 16);
        // lanes 0..3 now hold l[g = lane]

        const size_t obase = (((size_t)b * KVH + kvh) * NCH_TOT + ch) * (size_t)(G * HD);
        const size_t lbase = (((size_t)b * KVH + kvh) * NCH_TOT + ch) * (size_t)G;
        if (half == 0) {
            #pragma unroll
            for (int g = 0; g < G; g++)
                #pragma unroll
                for (int j = 0; j < 4; j++) {
                    int d = (j < 2 ? 0 : 64) + lr * 4 + (j & 1) * 2;
                    *(float2*)(g_po + obase + g * HD + d) = acc[g][j];
                }
            if (lr < 4) g_pl[lbase + lr] = lpart;
        }
    } else {
        // ============ Part B: levels 1+2, per-sequence ============
        const int bidx = grp * 3 + (rem - 4);
        const int b    = bidx & (BATCH - 1);
        const int kvh  = (bidx >> 5) & (KVH - 1);
        const int ch   = bidx >> 8;

        if (tid < B_CHP) {
            int vp = ch * B_CHP + tid;
            pages_s[tid] = (vp < L1P) ? p1[b * L1P + vp] : p2[b * L2P + (vp - L1P)];
        }

        float2 qr[G][4];
        {
            const float* qb = q + ((size_t)b * KVH + kvh) * G * HD;
            #pragma unroll
            for (int g = 0; g < G; g++) {
                float4 x = *(const float4*)(qb + g * HD + lr * 4);
                float4 y = *(const float4*)(qb + g * HD + 64 + lr * 4);
                qr[g][0] = make_float2(x.x * ATT_SCALE, x.y * ATT_SCALE);
                qr[g][1] = make_float2(x.z * ATT_SCALE, x.w * ATT_SCALE);
                qr[g][2] = make_float2(y.x * ATT_SCALE, y.y * ATT_SCALE);
                qr[g][3] = make_float2(y.z * ATT_SCALE, y.w * ATT_SCALE);
            }
        }
        __syncthreads();

        float lpart = 0.f;
        float2 acc[G][4];
        #pragma unroll
        for (int g = 0; g < G; g++)
            #pragma unroll
            for (int j = 0; j < 4; j++) acc[g][j] = make_float2(0.f, 0.f);

        auto rowptr = [&](int tok) -> const float* {
            int pg = pages_s[tok >> 4];
            int tp = tok & 15;
            return kv + (size_t)pg * PGSTR + (size_t)tp * KVROW + (size_t)kvh * HD;
        };

        const int mytok = warp * 2 + half;
        const float* p = rowptr(mytok);
        float4 k0 = *(const float4*)(p + lr * 4);
        float4 k1 = *(const float4*)(p + 64 + lr * 4);
        float4 v0 = *(const float4*)(p + VOFF + lr * 4);
        float4 v1 = *(const float4*)(p + VOFF + 64 + lr * 4);

        for (int it = 16; it <= 256; it += 16) {
            float4 nk0, nk1, nv0, nv1;
            if (it < 256) {
                const float* np = rowptr(it + mytok);
                nk0 = *(const float4*)(np + lr * 4);
                nk1 = *(const float4*)(np + 64 + lr * 4);
                nv0 = *(const float4*)(np + VOFF + lr * 4);
                nv1 = *(const float4*)(np + VOFF + 64 + lr * 4);
            }

            float2 kp[4] = { make_float2(k0.x,k0.y), make_float2(k0.z,k0.w),
                             make_float2(k1.x,k1.y), make_float2(k1.z,k1.w) };
            float2 vp[4] = { make_float2(v0.x,v0.y), make_float2(v0.z,v0.w),
                             make_float2(v1.x,v1.y), make_float2(v1.z,v1.w) };

            float s[G];
            #pragma unroll
            for (int g = 0; g < G; g++) {
                float2 t = fmul2(qr[g][0], kp[0]);
                t = ffma2(qr[g][1], kp[1], t);
                t = ffma2(qr[g][2], kp[2], t);
                t = ffma2(qr[g][3], kp[3], t);
                s[g] = t.x + t.y;
            }
            float e0, e1, e2, e3;
            half_softmax(s, lane, lpart, e0, e1, e2, e3);
            #pragma unroll
            for (int j = 0; j < 4; j++) {
                acc[0][j] = ffma2(make_float2(e0, e0), vp[j], acc[0][j]);
                acc[1][j] = ffma2(make_float2(e1, e1), vp[j], acc[1][j]);
                acc[2][j] = ffma2(make_float2(e2, e2), vp[j], acc[2][j]);
                acc[3][j] = ffma2(make_float2(e3, e3), vp[j], acc[3][j]);
            }

            k0 = nk0; k1 = nk1; v0 = nv0; v1 = nv1;
        }

        // merge halves (lpart: ONLY shfl 16)
        #pragma unroll
        for (int g = 0; g < G; g++)
            #pragma unroll
            for (int j = 0; j < 4; j++) {
                acc[g][j].x += __shfl_xor_sync(0xffffffffu, acc[g][j].x, 16);
                acc[g][j].y += __shfl_xor_sync(0xffffffffu, acc[g][j].y, 16);
            }
        lpart += __shfl_xor_sync(0xffffffffu, lpart, 16);

        if (half == 0) {
            #pragma unroll
            for (int g = 0; g < G; g++)
                #pragma unroll
                for (int j = 0; j < 4; j++) {
                    int d = (j < 2 ? 0 : 64) + lr * 4 + (j & 1) * 2;
                    *(float2*)(sbuf + warp * 512 + g * HD + d) = acc[g][j];
                }
            if (lr < 4) s_l[warp * G + lr] = lpart;
        }
        __syncthreads();

        const size_t obase = (((size_t)b * KVH + kvh) * NCH_TOT + (A_NCH + ch)) * (size_t)(G * HD);
        const size_t lbase = (((size_t)b * KVH + kvh) * NCH_TOT + (A_NCH + ch)) * (size_t)G;
        #pragma unroll
        for (int pidx = 0; pidx < 2; pidx++) {
            int p2i = tid + pidx * 256;
            float O = 0.f;
            #pragma unroll
            for (int w = 0; w < 8; w++) O += sbuf[w * 512 + p2i];
            g_po[obase + p2i] = O;
        }
        if (tid < G) {
            float L = 0.f;
            #pragma unroll
            for (int w = 0; w < 8; w++) L += s_l[w * G + tid];
            g_pl[lbase + tid] = L;
        }
    }
}

__global__ __launch_bounds__(512)
void cascade_phase2(float* __restrict__ out)
{
    const int b   = blockIdx.x;
    const int kvh = blockIdx.y;
    const int t   = threadIdx.x;
    const int sub = t >> 8;               // 0/1 chunk-split
    const int idx = t & 255;              // (g, d2) pair
    const int g   = idx >> 6;             // 0..3
    const int d2  = idx & 63;             // float2 slot 0..63

    __shared__ float spl[NCH_TOT * G];
    __shared__ float2 sred[256];
    for (int i = t; i < NCH_TOT * G; i += 512)
        spl[i] = g_pl[((size_t)b * KVH + kvh) * NCH_TOT * G + i];
    __syncthreads();

    float L = 0.f;
    #pragma unroll
    for (int ch = 0; ch < NCH_TOT; ch++) L += spl[ch * G + g];
    const float inv = 1.f / L;

    const float* pb = g_po + ((size_t)b * KVH + kvh) * NCH_TOT * (size_t)(G * HD)
                           + (size_t)g * HD + d2 * 2;
    float2 O = make_float2(0.f, 0.f);
    #pragma unroll
    for (int ch = sub; ch < NCH_TOT; ch += 2) {
        float2 v = *(const float2*)(pb + (size_t)ch * (G * HD));
        O.x += v.x; O.y += v.y;
    }
    if (sub == 1) sred[idx] = O;
    __syncthreads();
    if (sub == 0) {
        O.x = (O.x + sred[idx].x) * inv;
        O.y = (O.y + sred[idx].y) * inv;
        *(float2*)(out + ((size_t)b * KVH + kvh) * G * HD + (size_t)g * HD + d2 * 2) = O;
    }
}

extern "C" void kernel_launch(void* const* d_in, const int* in_sizes, int n_in,
                              void* d_out, int out_size)
{
    const float* q  = (const float*)d_in[0];
    const float* kv = (const float*)d_in[1];
    const int*   sp = (const int*)d_in[2];
    const int*   p1 = (const int*)d_in[3];
    const int*   p2 = (const int*)d_in[4];
    float* out = (float*)d_out;

    cascade_phase1<<<A_BLOCKS + B_BLOCKS, 256>>>(q, kv, sp, p1, p2);
    cascade_phase2<<<dim3(BATCH, KVH), 512>>>(out);
}

// round 14
// speedup vs baseline: 1.6876x; 1.1239x over previous
#include <cuda_runtime.h>
#include <cuda_bf16.h>
#include <cstdint>

#define BATCH 32
#define KVH 8
#define G 4
#define HD 128
#define PS 16
#define L0P 256
#define L1P 64
#define L2P 32
#define ATT_SCALE 0.08838834764831845f

// Part A (level 0, shared prefix): 4 batch-groups x 8 kvh x 64 chunks (4 pages)
#define A_BG 4
#define A_BPG 8
#define A_CHP 4
#define A_NCH 64
#define A_BLOCKS (A_BG * KVH * A_NCH)          // 2048
// Part B (levels 1+2, per-seq): 32 b x 8 kvh x 6 chunks (16 pages)
#define B_CHP 16
#define B_NCH 6
#define B_BLOCKS (BATCH * KVH * B_NCH)         // 1536
#define NCH_TOT (A_NCH + B_NCH)                // 70 partials per (b,kvh)

// cp.async tile pipeline: tile = 1 page = 16 tokens; K(2048f) + V(2048f) = 16KB
#define DEPTH 4
#define TILE_F 4096
#define SMEM_DYN (DEPTH * TILE_F * 4)          // 64KB dynamic smem

// unnormalized partial sums (fixed m=0 softmax; merge = plain add)
__device__ float g_po[(size_t)BATCH * KVH * NCH_TOT * G * HD];
__device__ float g_pl[(size_t)BATCH * KVH * NCH_TOT * G];

union F2u { float2 f2; unsigned long long u; };
__device__ __forceinline__ float2 ffma2(float2 a, float2 b, float2 c) {
    F2u A, B, C, R; A.f2 = a; B.f2 = b; C.f2 = c;
    asm("fma.rn.f32x2 %0, %1, %2, %3;" : "=l"(R.u) : "l"(A.u), "l"(B.u), "l"(C.u));
    return R.f2;
}
__device__ __forceinline__ float2 fmul2(float2 a, float2 b) {
    F2u A, B, R; A.f2 = a; B.f2 = b;
    asm("mul.rn.f32x2 %0, %1, %2;" : "=l"(R.u) : "l"(A.u), "l"(B.u));
    return R.f2;
}

__device__ __forceinline__ void cp16(uint32_t s, const float* g) {
    asm volatile("cp.async.cg.shared.global [%0], [%1], 16;" :: "r"(s), "l"(g));
}
__device__ __forceinline__ void cp_commit() {
    asm volatile("cp.async.commit_group;");
}
template <int N> __device__ __forceinline__ void cp_wait() {
    asm volatile("cp.async.wait_group %0;" :: "n"(N));
}

// reduce s[0..3] over the 16-lane half; ONE exp per lane (lane owns g=lane&3).
// lanes {x,x+4,x+8,x+12} hold IDENTICAL lpart copies -> final cross-half
// combine must be ONLY shfl_xor 16.
__device__ __forceinline__ void half_softmax(float s[4], int lane, float& lpart,
                                             float& e0, float& e1, float& e2, float& e3)
{
    #pragma unroll
    for (int off = 1; off <= 2; off <<= 1) {
        #pragma unroll
        for (int g = 0; g < 4; g++) s[g] += __shfl_xor_sync(0xffffffffu, s[g], off);
    }
    const int mg = lane & 3;
    float r = (mg == 0) ? s[0] : (mg == 1) ? s[1] : (mg == 2) ? s[2] : s[3];
    r += __shfl_xor_sync(0xffffffffu, r, 4);
    r += __shfl_xor_sync(0xffffffffu, r, 8);
    float e = __expf(r);
    lpart += e;
    const int base = lane & 16;
    e0 = __shfl_sync(0xffffffffu, e, base | 0);
    e1 = __shfl_sync(0xffffffffu, e, base | 1);
    e2 = __shfl_sync(0xffffffffu, e, base | 2);
    e3 = __shfl_sync(0xffffffffu, e, base | 3);
}

__global__ __launch_bounds__(256, 2)
void cascade_phase1(const float* __restrict__ q,
                    const float* __restrict__ kv,
                    const int* __restrict__ sp,
                    const int* __restrict__ p1,
                    const int* __restrict__ p2)
{
    extern __shared__ float stage[];               // DEPTH x (K 2048f | V 2048f)
    __shared__ int   pages_s[16];
    __shared__ float s_l[8 * G];

    const int tid  = threadIdx.x;
    const int warp = tid >> 5;
    const int lane = tid & 31;
    const int half = lane >> 4;
    const int lr   = lane & 15;

    // interleave A:B = 4:3 so compute-heavy A and stream-heavy B co-execute
    const int bx   = blockIdx.x;
    const int grp  = bx / 7;
    const int rem  = bx - grp * 7;
    const bool isA = (rem < 4);

    const size_t KVROW = (size_t)KVH * HD;
    const size_t VOFF  = (size_t)PS * KVH * HD;
    const size_t PGSTR = 2 * VOFF;

    int b, kvh, ch, ntiles;
    if (isA) {
        const int a = grp * 4 + rem;
        const int bg = a & (A_BG - 1);
        kvh = (a >> 2) & (KVH - 1);
        ch  = a >> 5;
        b   = bg * A_BPG + warp;                   // warp owns one batch
        ntiles = A_CHP;
        if (tid < A_CHP) pages_s[tid] = sp[ch * A_CHP + tid];
    } else {
        const int bidx = grp * 3 + (rem - 4);
        b   = bidx & (BATCH - 1);
        kvh = (bidx >> 5) & (KVH - 1);
        ch  = bidx >> 8;
        ntiles = B_CHP;
        if (tid < B_CHP) {
            int vp = ch * B_CHP + tid;
            pages_s[tid] = (vp < L1P) ? p1[b * L1P + vp] : p2[b * L2P + (vp - L1P)];
        }
    }
    __syncthreads();                               // pages visible before staging

    const uint32_t sbase = (uint32_t)__cvta_generic_to_shared(stage);

    // q as packed float2 pairs, pre-scaled
    float2 qr[G][4];
    {
        const float* qb = q + ((size_t)b * KVH + kvh) * G * HD;
        #pragma unroll
        for (int g = 0; g < G; g++) {
            float4 x = *(const float4*)(qb + g * HD + lr * 4);
            float4 y = *(const float4*)(qb + g * HD + 64 + lr * 4);
            qr[g][0] = make_float2(x.x * ATT_SCALE, x.y * ATT_SCALE);
            qr[g][1] = make_float2(x.z * ATT_SCALE, x.w * ATT_SCALE);
            qr[g][2] = make_float2(y.x * ATT_SCALE, y.y * ATT_SCALE);
            qr[g][3] = make_float2(y.z * ATT_SCALE, y.w * ATT_SCALE);
        }
    }

    float lpart = 0.f;
    float2 acc[G][4];
    #pragma unroll
    for (int g = 0; g < G; g++)
        #pragma unroll
        for (int j = 0; j < 4; j++) acc[g][j] = make_float2(0.f, 0.f);

    // gmem->smem staging of tile t (one page: K plane + V plane, kvh slice)
    auto stage_tile = [&](int t) {
        const int pg = pages_s[t];
        const float* base = kv + (size_t)pg * PGSTR + (size_t)kvh * HD;
        const uint32_t sb = sbase + (uint32_t)((t % DEPTH) * TILE_F) * 4u;
        #pragma unroll
        for (int j = 0; j < 4; j++) {
            int idx   = tid + j * 256;             // 0..1023 granules of 16B
            int plane = idx >> 9;                  // 0=K, 1=V
            int r     = idx & 511;
            int tok   = r >> 5;
            int gg    = r & 31;
            const float* gp = base + (size_t)plane * VOFF + (size_t)tok * KVROW + gg * 4;
            uint32_t sa = sb + (uint32_t)(plane * 2048 + tok * 128 + gg * 4) * 4u;
            cp16(sa, gp);
        }
    };

    // compute one token pair slot (token row pointers into smem)
    auto proc = [&](const float* kr, const float* vr) {
        float4 k0 = *(const float4*)(kr + lr * 4);
        float4 k1 = *(const float4*)(kr + 64 + lr * 4);
        float4 v0 = *(const float4*)(vr + lr * 4);
        float4 v1 = *(const float4*)(vr + 64 + lr * 4);

        float2 kp[4] = { make_float2(k0.x,k0.y), make_float2(k0.z,k0.w),
                         make_float2(k1.x,k1.y), make_float2(k1.z,k1.w) };
        float2 vv[4] = { make_float2(v0.x,v0.y), make_float2(v0.z,v0.w),
                         make_float2(v1.x,v1.y), make_float2(v1.z,v1.w) };

        float s[G];
        #pragma unroll
        for (int g = 0; g < G; g++) {
            float2 t2 = fmul2(qr[g][0], kp[0]);
            t2 = ffma2(qr[g][1], kp[1], t2);
            t2 = ffma2(qr[g][2], kp[2], t2);
            t2 = ffma2(qr[g][3], kp[3], t2);
            s[g] = t2.x + t2.y;
        }
        float e0, e1, e2, e3;
        half_softmax(s, lane, lpart, e0, e1, e2, e3);
        #pragma unroll
        for (int j = 0; j < 4; j++) {
            acc[0][j] = ffma2(make_float2(e0, e0), vv[j], acc[0][j]);
            acc[1][j] = ffma2(make_float2(e1, e1), vv[j], acc[1][j]);
            acc[2][j] = ffma2(make_float2(e2, e2), vv[j], acc[2][j]);
            acc[3][j] = ffma2(make_float2(e3, e3), vv[j], acc[3][j]);
        }
    };

    // pipeline prologue: stage tiles 0..DEPTH-2
    #pragma unroll
    for (int t = 0; t < DEPTH - 1; t++) {
        if (t < ntiles) stage_tile(t);
        cp_commit();
    }

    // main pipeline
    for (int t = 0; t < ntiles; t++) {
        cp_wait<DEPTH - 2>();                      // tile t complete (order-based)
        __syncthreads();                           // visible to all; fences t-1 reads
        if (t + DEPTH - 1 < ntiles) stage_tile(t + DEPTH - 1);  // overwrites buf of t-1
        cp_commit();

        const float* kbuf = stage + (t % DEPTH) * TILE_F;
        const float* vbuf = kbuf + 2048;
        if (isA) {
            #pragma unroll
            for (int it = 0; it < 16; it += 2) {
                const int tok = it + half;
                proc(kbuf + tok * 128, vbuf + tok * 128);
            }
        } else {
            const int tok = warp * 2 + half;
            proc(kbuf + tok * 128, vbuf + tok * 128);
        }
    }

    // cross-half merge (lpart: ONLY shfl 16 — see half_softmax note)
    #pragma unroll
    for (int g = 0; g < G; g++)
        #pragma unroll
        for (int j = 0; j < 4; j++) {
            acc[g][j].x += __shfl_xor_sync(0xffffffffu, acc[g][j].x, 16);
            acc[g][j].y += __shfl_xor_sync(0xffffffffu, acc[g][j].y, 16);
        }
    lpart += __shfl_xor_sync(0xffffffffu, lpart, 16);
    // lanes 0..3 hold l[g = lane]

    if (isA) {
        const size_t obase = (((size_t)b * KVH + kvh) * NCH_TOT + ch) * (size_t)(G * HD);
        const size_t lbase = (((size_t)b * KVH + kvh) * NCH_TOT + ch) * (size_t)G;
        if (half == 0) {
            #pragma unroll
            for (int g = 0; g < G; g++)
                #pragma unroll
                for (int j = 0; j < 4; j++) {
                    int d = (j < 2 ? 0 : 64) + lr * 4 + (j & 1) * 2;
                    *(float2*)(g_po + obase + g * HD + d) = acc[g][j];
                }
            if (lr < 4) g_pl[lbase + lr] = lpart;
        }
    } else {
        // B: merge 8 warp states via smem (reuse stage ring after pipeline drains)
        cp_wait<0>();
        __syncthreads();
        if (half == 0) {
            #pragma unroll
            for (int g = 0; g < G; g++)
                #pragma unroll
                for (int j = 0; j < 4; j++) {
                    int d = (j < 2 ? 0 : 64) + lr * 4 + (j & 1) * 2;
                    *(float2*)(stage + warp * 512 + g * HD + d) = acc[g][j];
                }
            if (lr < 4) s_l[warp * G + lr] = lpart;
        }
        __syncthreads();

        const size_t obase = (((size_t)b * KVH + kvh) * NCH_TOT + (A_NCH + ch)) * (size_t)(G * HD);
        const size_t lbase = (((size_t)b * KVH + kvh) * NCH_TOT + (A_NCH + ch)) * (size_t)G;
        #pragma unroll
        for (int pidx = 0; pidx < 2; pidx++) {
            int p2i = tid + pidx * 256;
            float O = 0.f;
            #pragma unroll
            for (int w = 0; w < 8; w++) O += stage[w * 512 + p2i];
            g_po[obase + p2i] = O;
        }
        if (tid < G) {
            float L = 0.f;
            #pragma unroll
            for (int w = 0; w < 8; w++) L += s_l[w * G + tid];
            g_pl[lbase + tid] = L;
        }
    }
}

__global__ __launch_bounds__(512)
void cascade_phase2(float* __restrict__ out)
{
    const int b   = blockIdx.x;
    const int kvh = blockIdx.y;
    const int t   = threadIdx.x;
    const int sub = t >> 8;               // 0/1 chunk-split
    const int idx = t & 255;              // (g, d2) pair
    const int g   = idx >> 6;             // 0..3
    const int d2  = idx & 63;             // float2 slot 0..63

    __shared__ float spl[NCH_TOT * G];
    __shared__ float2 sred[256];
    for (int i = t; i < NCH_TOT * G; i += 512)
        spl[i] = g_pl[((size_t)b * KVH + kvh) * NCH_TOT * G + i];
    __syncthreads();

    float L = 0.f;
    #pragma unroll
    for (int ch = 0; ch < NCH_TOT; ch++) L += spl[ch * G + g];
    const float inv = 1.f / L;

    const float* pb = g_po + ((size_t)b * KVH + kvh) * NCH_TOT * (size_t)(G * HD)
                           + (size_t)g * HD + d2 * 2;
    float2 O = make_float2(0.f, 0.f);
    #pragma unroll
    for (int ch = sub; ch < NCH_TOT; ch += 2) {
        float2 v = *(const float2*)(pb + (size_t)ch * (G * HD));
        O.x += v.x; O.y += v.y;
    }
    if (sub == 1) sred[idx] = O;
    __syncthreads();
    if (sub == 0) {
        O.x = (O.x + sred[idx].x) * inv;
        O.y = (O.y + sred[idx].y) * inv;
        *(float2*)(out + ((size_t)b * KVH + kvh) * G * HD + (size_t)g * HD + d2 * 2) = O;
    }
}

extern "C" void kernel_launch(void* const* d_in, const int* in_sizes, int n_in,
                              void* d_out, int out_size)
{
    const float* q  = (const float*)d_in[0];
    const float* kv = (const float*)d_in[1];
    const int*   sp = (const int*)d_in[2];
    const int*   p1 = (const int*)d_in[3];
    const int*   p2 = (const int*)d_in[4];
    float* out = (float*)d_out;

    cudaFuncSetAttribute(cascade_phase1,
                         cudaFuncAttributeMaxDynamicSharedMemorySize, SMEM_DYN);
    cascade_phase1<<<A_BLOCKS + B_BLOCKS, 256, SMEM_DYN>>>(q, kv, sp, p1, p2);
    cascade_phase2<<<dim3(BATCH, KVH), 512>>>(out);
}

// round 15
// speedup vs baseline: 1.7793x; 1.0544x over previous
#include <cuda_runtime.h>
#include <cuda_bf16.h>
#include <cstdint>

#define BATCH 32
#define KVH 8
#define G 4
#define HD 128
#define PS 16
#define L0P 256
#define L1P 64
#define L2P 32
#define ATT_SCALE 0.08838834764831845f

// Part A (level 0, shared prefix): 4 batch-groups x 8 kvh x 64 chunks (4 pages)
#define A_BG 4
#define A_BPG 8
#define A_CHP 4
#define A_NCH 64
#define A_BLOCKS (A_BG * KVH * A_NCH)          // 2048
// Part B (levels 1+2, per-seq): 32 b x 8 kvh x 6 chunks (16 pages)
#define B_CHP 16
#define B_NCH 6
#define B_BLOCKS (BATCH * KVH * B_NCH)         // 1536
#define NCH_TOT (A_NCH + B_NCH)                // 70 partials per (b,kvh)

// cp.async pipeline: TILE = 2 pages = 32 tokens = 32KB; ring of 3 tiles (6 page slots)
#define PAGE_F 4096                            // floats per page slot (K 2048 | V 2048)
#define NPSLOT 6
#define SMEM_DYN (NPSLOT * PAGE_F * 4)         // 96KB dynamic smem

// unnormalized partial sums (fixed m=0 softmax; merge = plain add)
__device__ float g_po[(size_t)BATCH * KVH * NCH_TOT * G * HD];
__device__ float g_pl[(size_t)BATCH * KVH * NCH_TOT * G];

union F2u { float2 f2; unsigned long long u; };
__device__ __forceinline__ float2 ffma2(float2 a, float2 b, float2 c) {
    F2u A, B, C, R; A.f2 = a; B.f2 = b; C.f2 = c;
    asm("fma.rn.f32x2 %0, %1, %2, %3;" : "=l"(R.u) : "l"(A.u), "l"(B.u), "l"(C.u));
    return R.f2;
}
__device__ __forceinline__ float2 fmul2(float2 a, float2 b) {
    F2u A, B, R; A.f2 = a; B.f2 = b;
    asm("mul.rn.f32x2 %0, %1, %2;" : "=l"(R.u) : "l"(A.u), "l"(B.u));
    return R.f2;
}

__device__ __forceinline__ void cp16(uint32_t s, const float* g) {
    asm volatile("cp.async.cg.shared.global [%0], [%1], 16;" :: "r"(s), "l"(g));
}
__device__ __forceinline__ void cp_commit() {
    asm volatile("cp.async.commit_group;");
}
template <int N> __device__ __forceinline__ void cp_wait() {
    asm volatile("cp.async.wait_group %0;" :: "n"(N));
}

// reduce s[0..3] over the 16-lane half; ONE exp per lane (lane owns g=lane&3).
// lanes {x,x+4,x+8,x+12} hold IDENTICAL lpart copies -> final cross-half
// combine must be ONLY shfl_xor 16.
__device__ __forceinline__ void half_softmax(float s[4], int lane, float& lpart,
                                             float& e0, float& e1, float& e2, float& e3)
{
    #pragma unroll
    for (int off = 1; off <= 2; off <<= 1) {
        #pragma unroll
        for (int g = 0; g < 4; g++) s[g] += __shfl_xor_sync(0xffffffffu, s[g], off);
    }
    const int mg = lane & 3;
    float r = (mg == 0) ? s[0] : (mg == 1) ? s[1] : (mg == 2) ? s[2] : s[3];
    r += __shfl_xor_sync(0xffffffffu, r, 4);
    r += __shfl_xor_sync(0xffffffffu, r, 8);
    float e = __expf(r);
    lpart += e;
    const int base = lane & 16;
    e0 = __shfl_sync(0xffffffffu, e, base | 0);
    e1 = __shfl_sync(0xffffffffu, e, base | 1);
    e2 = __shfl_sync(0xffffffffu, e, base | 2);
    e3 = __shfl_sync(0xffffffffu, e, base | 3);
}

__global__ __launch_bounds__(256, 2)
void cascade_phase1(const float* __restrict__ q,
                    const float* __restrict__ kv,
                    const int* __restrict__ sp,
                    const int* __restrict__ p1,
                    const int* __restrict__ p2)
{
    extern __shared__ float stage[];               // NPSLOT page slots
    __shared__ int   pages_s[16];
    __shared__ float s_l[8 * G];

    const int tid  = threadIdx.x;
    const int warp = tid >> 5;
    const int lane = tid & 31;
    const int half = lane >> 4;
    const int lr   = lane & 15;

    // interleave A:B = 4:3 so compute-heavy A and stream-heavy B co-execute
    const int bx   = blockIdx.x;
    const int grp  = bx / 7;
    const int rem  = bx - grp * 7;
    const bool isA = (rem < 4);

    const size_t KVROW = (size_t)KVH * HD;
    const size_t VOFF  = (size_t)PS * KVH * HD;
    const size_t PGSTR = 2 * VOFF;

    int b, kvh, ch, npages;
    if (isA) {
        const int a = grp * 4 + rem;
        const int bg = a & (A_BG - 1);
        kvh = (a >> 2) & (KVH - 1);
        ch  = a >> 5;
        b   = bg * A_BPG + warp;                   // warp owns one batch
        npages = A_CHP;                            // 4 pages = 2 tiles
        if (tid < A_CHP) pages_s[tid] = sp[ch * A_CHP + tid];
    } else {
        const int bidx = grp * 3 + (rem - 4);
        b   = bidx & (BATCH - 1);
        kvh = (bidx >> 5) & (KVH - 1);
        ch  = bidx >> 8;
        npages = B_CHP;                            // 16 pages = 8 tiles
        if (tid < B_CHP) {
            int vp = ch * B_CHP + tid;
            pages_s[tid] = (vp < L1P) ? p1[b * L1P + vp] : p2[b * L2P + (vp - L1P)];
        }
    }
    const int ntiles = npages >> 1;
    __syncthreads();                               // pages visible before staging

    const uint32_t sbase = (uint32_t)__cvta_generic_to_shared(stage);

    // q as packed float2 pairs, pre-scaled
    float2 qr[G][4];
    {
        const float* qb = q + ((size_t)b * KVH + kvh) * G * HD;
        #pragma unroll
        for (int g = 0; g < G; g++) {
            float4 x = *(const float4*)(qb + g * HD + lr * 4);
            float4 y = *(const float4*)(qb + g * HD + 64 + lr * 4);
            qr[g][0] = make_float2(x.x * ATT_SCALE, x.y * ATT_SCALE);
            qr[g][1] = make_float2(x.z * ATT_SCALE, x.w * ATT_SCALE);
            qr[g][2] = make_float2(y.x * ATT_SCALE, y.y * ATT_SCALE);
            qr[g][3] = make_float2(y.z * ATT_SCALE, y.w * ATT_SCALE);
        }
    }

    float lpart = 0.f;
    float2 acc[G][4];
    #pragma unroll
    for (int g = 0; g < G; g++)
        #pragma unroll
        for (int j = 0; j < 4; j++) acc[g][j] = make_float2(0.f, 0.f);

    // gmem->smem staging of one page p (K plane + V plane, kvh slice) -> slot p%6
    auto stage_page = [&](int p) {
        const int pg = pages_s[p];
        const float* base = kv + (size_t)pg * PGSTR + (size_t)kvh * HD;
        const uint32_t sb = sbase + (uint32_t)((p % NPSLOT) * PAGE_F) * 4u;
        #pragma unroll
        for (int j = 0; j < 4; j++) {
            int idx   = tid + j * 256;             // 0..1023 granules of 16B
            int plane = idx >> 9;                  // 0=K, 1=V
            int r     = idx & 511;
            int tok   = r >> 5;
            int gg    = r & 31;
            const float* gp = base + (size_t)plane * VOFF + (size_t)tok * KVROW + gg * 4;
            uint32_t sa = sb + (uint32_t)(plane * 2048 + tok * 128 + gg * 4) * 4u;
            cp16(sa, gp);
        }
    };

    // compute one token (row pointers into smem)
    auto proc = [&](const float* kr, const float* vr) {
        float4 k0 = *(const float4*)(kr + lr * 4);
        float4 k1 = *(const float4*)(kr + 64 + lr * 4);
        float4 v0 = *(const float4*)(vr + lr * 4);
        float4 v1 = *(const float4*)(vr + 64 + lr * 4);

        float2 kp[4] = { make_float2(k0.x,k0.y), make_float2(k0.z,k0.w),
                         make_float2(k1.x,k1.y), make_float2(k1.z,k1.w) };
        float2 vv[4] = { make_float2(v0.x,v0.y), make_float2(v0.z,v0.w),
                         make_float2(v1.x,v1.y), make_float2(v1.z,v1.w) };

        float s[G];
        #pragma unroll
        for (int g = 0; g < G; g++) {
            float2 t2 = fmul2(qr[g][0], kp[0]);
            t2 = ffma2(qr[g][1], kp[1], t2);
            t2 = ffma2(qr[g][2], kp[2], t2);
            t2 = ffma2(qr[g][3], kp[3], t2);
            s[g] = t2.x + t2.y;
        }
        float e0, e1, e2, e3;
        half_softmax(s, lane, lpart, e0, e1, e2, e3);
        #pragma unroll
        for (int j = 0; j < 4; j++) {
            acc[0][j] = ffma2(make_float2(e0, e0), vv[j], acc[0][j]);
            acc[1][j] = ffma2(make_float2(e1, e1), vv[j], acc[1][j]);
            acc[2][j] = ffma2(make_float2(e2, e2), vv[j], acc[2][j]);
            acc[3][j] = ffma2(make_float2(e3, e3), vv[j], acc[3][j]);
        }
    };

    // pipeline prologue: stage tiles 0 and 1 (pages 0..3), one commit group per tile
    #pragma unroll
    for (int t = 0; t < 2; t++) {
        if (2 * t     < npages) stage_page(2 * t);
        if (2 * t + 1 < npages) stage_page(2 * t + 1);
        cp_commit();
    }

    // main pipeline: at iter t, groups cover tiles 0..t+1; wait<1> -> tile t ready
    for (int t = 0; t < ntiles; t++) {
        cp_wait<1>();
        __syncthreads();                           // all readers of tile t-1 done
        if (t + 2 < ntiles) {                      // stage tile t+2 (slots of t-1)
            stage_page(2 * t + 4);
            stage_page(2 * t + 5);
        }
        cp_commit();

        #pragma unroll
        for (int p = 0; p < 2; p++) {
            const float* kbuf = stage + ((2 * t + p) % NPSLOT) * PAGE_F;
            const float* vbuf = kbuf + 2048;
            if (isA) {
                #pragma unroll
                for (int it = 0; it < 16; it += 2) {
                    const int tok = it + half;
                    proc(kbuf + tok * 128, vbuf + tok * 128);
                }
            } else {
                const int tok = warp * 2 + half;
                proc(kbuf + tok * 128, vbuf + tok * 128);
            }
        }
    }

    // cross-half merge (lpart: ONLY shfl 16 — see half_softmax note)
    #pragma unroll
    for (int g = 0; g < G; g++)
        #pragma unroll
        for (int j = 0; j < 4; j++) {
            acc[g][j].x += __shfl_xor_sync(0xffffffffu, acc[g][j].x, 16);
            acc[g][j].y += __shfl_xor_sync(0xffffffffu, acc[g][j].y, 16);
        }
    lpart += __shfl_xor_sync(0xffffffffu, lpart, 16);
    // lanes 0..3 hold l[g = lane]

    if (isA) {
        const size_t obase = (((size_t)b * KVH + kvh) * NCH_TOT + ch) * (size_t)(G * HD);
        const size_t lbase = (((size_t)b * KVH + kvh) * NCH_TOT + ch) * (size_t)G;
        if (half == 0) {
            #pragma unroll
            for (int g = 0; g < G; g++)
                #pragma unroll
                for (int j = 0; j < 4; j++) {
                    int d = (j < 2 ? 0 : 64) + lr * 4 + (j & 1) * 2;
                    *(float2*)(g_po + obase + g * HD + d) = acc[g][j];
                }
            if (lr < 4) g_pl[lbase + lr] = lpart;
        }
    } else {
        // B: merge 8 warp states via smem (reuse stage ring after pipeline drains)
        cp_wait<0>();
        __syncthreads();
        if (half == 0) {
            #pragma unroll
            for (int g = 0; g < G; g++)
                #pragma unroll
                for (int j = 0; j < 4; j++) {
                    int d = (j < 2 ? 0 : 64) + lr * 4 + (j & 1) * 2;
                    *(float2*)(stage + warp * 512 + g * HD + d) = acc[g][j];
                }
            if (lr < 4) s_l[warp * G + lr] = lpart;
        }
        __syncthreads();

        const size_t obase = (((size_t)b * KVH + kvh) * NCH_TOT + (A_NCH + ch)) * (size_t)(G * HD);
        const size_t lbase = (((size_t)b * KVH + kvh) * NCH_TOT + (A_NCH + ch)) * (size_t)G;
        #pragma unroll
        for (int pidx = 0; pidx < 2; pidx++) {
            int p2i = tid + pidx * 256;
            float O = 0.f;
            #pragma unroll
            for (int w = 0; w < 8; w++) O += stage[w * 512 + p2i];
            g_po[obase + p2i] = O;
        }
        if (tid < G) {
            float L = 0.f;
            #pragma unroll
            for (int w = 0; w < 8; w++) L += s_l[w * G + tid];
            g_pl[lbase + tid] = L;
        }
    }
}

__global__ __launch_bounds__(1024)
void cascade_phase2(float* __restrict__ out)
{
    const int b   = blockIdx.x;
    const int kvh = blockIdx.y;
    const int t   = threadIdx.x;
    const int sub = t >> 8;               // 0..3 chunk-split
    const int idx = t & 255;              // (g, d2) pair
    const int g   = idx >> 6;             // 0..3
    const int d2  = idx & 63;             // float2 slot 0..63

    __shared__ float spl[NCH_TOT * G];
    __shared__ float2 sred[3][256];
    for (int i = t; i < NCH_TOT * G; i += 1024)
        spl[i] = g_pl[((size_t)b * KVH + kvh) * NCH_TOT * G + i];
    __syncthreads();

    float L = 0.f;
    #pragma unroll
    for (int ch = 0; ch < NCH_TOT; ch++) L += spl[ch * G + g];
    const float inv = 1.f / L;

    const float* pb = g_po + ((size_t)b * KVH + kvh) * NCH_TOT * (size_t)(G * HD)
                           + (size_t)g * HD + d2 * 2;
    float2 O = make_float2(0.f, 0.f);
    #pragma unroll
    for (int ch = sub; ch < NCH_TOT; ch += 4) {
        float2 v = *(const float2*)(pb + (size_t)ch * (G * HD));
        O.x += v.x; O.y += v.y;
    }
    if (sub > 0) sred[sub - 1][idx] = O;
    __syncthreads();
    if (sub == 0) {
        #pragma unroll
        for (int s2 = 0; s2 < 3; s2++) {
            O.x += sred[s2][idx].x;
            O.y += sred[s2][idx].y;
        }
        O.x *= inv; O.y *= inv;
        *(float2*)(out + ((size_t)b * KVH + kvh) * G * HD + (size_t)g * HD + d2 * 2) = O;
    }
}

extern "C" void kernel_launch(void* const* d_in, const int* in_sizes, int n_in,
                              void* d_out, int out_size)
{
    const float* q  = (const float*)d_in[0];
    const float* kv = (const float*)d_in[1];
    const int*   sp = (const int*)d_in[2];
    const int*   p1 = (const int*)d_in[3];
    const int*   p2 = (const int*)d_in[4];
    float* out = (float*)d_out;

    cudaFuncSetAttribute(cascade_phase1,
                         cudaFuncAttributeMaxDynamicSharedMemorySize, SMEM_DYN);
    cascade_phase1<<<A_BLOCKS + B_BLOCKS, 256, SMEM_DYN>>>(q, kv, sp, p1, p2);
    cascade_phase2<<<dim3(BATCH, KVH), 1024>>>(out);
}